// round 1
// baseline (speedup 1.0000x reference)
#include <cuda_runtime.h>

#define NND 100000
#define NE  1200000
#define DD  64
#define NG  100
#define BN_EPS 1e-5

// ---------------- scratch (device globals; no runtime allocation) ----------
__device__ float  g_bufA[NND * DD];
__device__ float  g_bufB[NND * DD];
__device__ double g_sum[DD];
__device__ double g_sumsq[DD];
__device__ float  g_scale[DD];
__device__ float  g_shift[DD];
__device__ float  g_pool[NG * DD];
__device__ int    g_cnt[NG];

__device__ __forceinline__ float* bufp(int b) { return b ? g_bufB : g_bufA; }

// ---------------- zeroing ---------------------------------------------------
__global__ void k_zero_all() {
    int t = blockIdx.x * blockDim.x + threadIdx.x;
    if (t < DD) { g_sum[t] = 0.0; g_sumsq[t] = 0.0; }
    if (t < NG * DD) g_pool[t] = 0.f;
    if (t < NG) g_cnt[t] = 0;
}

__global__ void k_zero_stats() {
    int t = threadIdx.x;
    if (t < DD) { g_sum[t] = 0.0; g_sumsq[t] = 0.0; }
}

// ---------------- copy (agg init: agg = h) ---------------------------------
__global__ void k_copy(const float4* __restrict__ ext, int srcsel, int dstb) {
    int t = blockIdx.x * blockDim.x + threadIdx.x;
    if (t >= NND * DD / 4) return;
    const float4* s = (srcsel < 0) ? ext : (const float4*)bufp(srcsel);
    ((float4*)bufp(dstb))[t] = s[t];
}

// ---------------- edge scatter: agg[dst] += h[src] --------------------------
// 16 threads per edge, each handles one float4 of the 64-wide row.
__global__ void k_scatter(const float* ext, int srcsel, int dstb,
                          const int* __restrict__ src, const int* __restrict__ dst) {
    int t = blockIdx.x * blockDim.x + threadIdx.x;
    if (t >= NE * 16) return;
    int e = t >> 4;
    int c = t & 15;
    const float4* h = (const float4*)((srcsel < 0) ? ext : bufp(srcsel));
    int s = __ldg(src + e);
    int d = __ldg(dst + e);
    float4 v = __ldg(h + s * 16 + c);
    float* p = bufp(dstb) + d * 64 + c * 4;
    atomicAdd(p + 0, v.x);
    atomicAdd(p + 1, v.y);
    atomicAdd(p + 2, v.z);
    atomicAdd(p + 3, v.w);
}

// ---------------- Y = X @ W + b (thread per row, W in smem) -----------------
__global__ __launch_bounds__(128) void k_lin1(int inb, int outb,
        const float* __restrict__ W, const float* __restrict__ bias) {
    __shared__ float Ws[DD * DD];
    __shared__ float bs[DD];
    for (int i = threadIdx.x; i < DD * DD; i += 128) Ws[i] = W[i];
    if (threadIdx.x < DD) bs[threadIdx.x] = bias[threadIdx.x];
    __syncthreads();

    int row = blockIdx.x * 128 + threadIdx.x;
    if (row >= NND) return;
    const float* X = bufp(inb);
    float*       Y = bufp(outb);

    float x[DD];
    const float4* xp = (const float4*)(X + row * DD);
#pragma unroll
    for (int i = 0; i < 16; i++) {
        float4 v = xp[i];
        x[4 * i + 0] = v.x; x[4 * i + 1] = v.y; x[4 * i + 2] = v.z; x[4 * i + 3] = v.w;
    }

    float4* yp = (float4*)(Y + row * DD);
#pragma unroll 1
    for (int half = 0; half < 2; half++) {
        float acc[32];
#pragma unroll
        for (int j = 0; j < 32; j++) acc[j] = bs[half * 32 + j];
#pragma unroll
        for (int k = 0; k < DD; k++) {
            float xk = x[k];
            const float* wr = &Ws[k * DD + half * 32];
#pragma unroll
            for (int j = 0; j < 32; j++) acc[j] = fmaf(xk, wr[j], acc[j]);
        }
#pragma unroll
        for (int j = 0; j < 8; j++)
            yp[half * 8 + j] = make_float4(acc[4 * j], acc[4 * j + 1], acc[4 * j + 2], acc[4 * j + 3]);
    }
}

// ---------------- per-column sum / sumsq over rows (double accumulate) ------
__global__ void k_bn_stats(int inb) {
    const float* Y = bufp(inb);
    int col = threadIdx.x & 63;
    int rg  = threadIdx.x >> 6;          // 0..3
    int r0  = blockIdx.x * 1024 + rg * 256;
    float s = 0.f, sq = 0.f;
    for (int i = 0; i < 256; i++) {
        int r = r0 + i;
        if (r < NND) {
            float v = Y[r * 64 + col];
            s += v;
            sq += v * v;
        }
    }
    __shared__ float ss[256], ssq[256];
    ss[threadIdx.x] = s; ssq[threadIdx.x] = sq;
    __syncthreads();
    if (rg == 0) {
        float ts  = ss[col] + ss[64 + col] + ss[128 + col] + ss[192 + col];
        float tsq = ssq[col] + ssq[64 + col] + ssq[128 + col] + ssq[192 + col];
        atomicAdd(&g_sum[col], (double)ts);
        atomicAdd(&g_sumsq[col], (double)tsq);
    }
}

// ---------------- BN affine params ------------------------------------------
__global__ void k_bn_params(const float* __restrict__ gamma, const float* __restrict__ beta) {
    int j = threadIdx.x;
    if (j >= DD) return;
    double mu  = g_sum[j] / (double)NND;
    double var = g_sumsq[j] / (double)NND - mu * mu;
    double inv = rsqrt(var + (double)BN_EPS);
    g_scale[j] = (float)((double)gamma[j] * inv);
    g_shift[j] = (float)((double)beta[j] - mu * (double)gamma[j] * inv);
}

// ---------------- Out = [relu]( relu(BN(Ypre)) @ W2 + b2 ) ------------------
__global__ __launch_bounds__(128) void k_mlp2(int inb, int outb,
        const float* __restrict__ W, const float* __restrict__ bias, int relu_out) {
    __shared__ float Ws[DD * DD];
    __shared__ float bs[DD], sc[DD], sh[DD];
    for (int i = threadIdx.x; i < DD * DD; i += 128) Ws[i] = W[i];
    if (threadIdx.x < DD) {
        bs[threadIdx.x] = bias[threadIdx.x];
        sc[threadIdx.x] = g_scale[threadIdx.x];
        sh[threadIdx.x] = g_shift[threadIdx.x];
    }
    __syncthreads();

    int row = blockIdx.x * 128 + threadIdx.x;
    if (row >= NND) return;
    const float* X = bufp(inb);
    float*       Y = bufp(outb);

    float x[DD];
    const float4* xp = (const float4*)(X + row * DD);
#pragma unroll
    for (int i = 0; i < 16; i++) {
        float4 v = xp[i];
        x[4 * i + 0] = v.x; x[4 * i + 1] = v.y; x[4 * i + 2] = v.z; x[4 * i + 3] = v.w;
    }
#pragma unroll
    for (int k = 0; k < DD; k++)
        x[k] = fmaxf(fmaf(x[k], sc[k], sh[k]), 0.f);

    float4* yp = (float4*)(Y + row * DD);
#pragma unroll 1
    for (int half = 0; half < 2; half++) {
        float acc[32];
#pragma unroll
        for (int j = 0; j < 32; j++) acc[j] = bs[half * 32 + j];
#pragma unroll
        for (int k = 0; k < DD; k++) {
            float xk = x[k];
            const float* wr = &Ws[k * DD + half * 32];
#pragma unroll
            for (int j = 0; j < 32; j++) acc[j] = fmaf(xk, wr[j], acc[j]);
        }
        if (relu_out) {
#pragma unroll
            for (int j = 0; j < 32; j++) acc[j] = fmaxf(acc[j], 0.f);
        }
#pragma unroll
        for (int j = 0; j < 8; j++)
            yp[half * 8 + j] = make_float4(acc[4 * j], acc[4 * j + 1], acc[4 * j + 2], acc[4 * j + 3]);
    }
}

// ---------------- per-graph node counts -------------------------------------
__global__ void k_count(const int* __restrict__ gid) {
    int t = blockIdx.x * blockDim.x + threadIdx.x;
    if (t < NND) atomicAdd(&g_cnt[__ldg(gid + t)], 1);
}

// ---------------- mean-pool (graph_ids sorted: run-length accumulate) -------
__global__ void k_pool(int inb, const int* __restrict__ gid) {
    const float* H = bufp(inb);
    int col = threadIdx.x & 63;
    int rg  = threadIdx.x >> 6;
    int r0  = blockIdx.x * 1024 + rg * 256;
    int cur = -1;
    float acc = 0.f;
    for (int i = 0; i < 256; i++) {
        int r = r0 + i;
        if (r >= NND) break;
        int gi = __ldg(gid + r);
        if (gi != cur) {
            if (cur >= 0) atomicAdd(&g_pool[cur * DD + col], acc);
            cur = gi;
            acc = 0.f;
        }
        acc += H[r * 64 + col];
    }
    if (cur >= 0) atomicAdd(&g_pool[cur * DD + col], acc);
}

__global__ void k_finalize(float* __restrict__ out) {
    int t = blockIdx.x * blockDim.x + threadIdx.x;
    if (t < NG * DD) {
        int g = t / DD;
        int c = g_cnt[g];
        float cf = (float)(c > 0 ? c : 1);
        out[t] = g_pool[t] / cf;
    }
}

// ---------------- launch -----------------------------------------------------
extern "C" void kernel_launch(void* const* d_in, const int* in_sizes, int n_in,
                              void* d_out, int out_size) {
    const float* feats = (const float*)d_in[0];
    const float* W1_0 = (const float*)d_in[1];
    const float* b1_0 = (const float*)d_in[2];
    const float* g_0  = (const float*)d_in[3];
    const float* bt_0 = (const float*)d_in[4];
    const float* W2_0 = (const float*)d_in[5];
    const float* b2_0 = (const float*)d_in[6];
    const float* W1_1 = (const float*)d_in[7];
    const float* b1_1 = (const float*)d_in[8];
    const float* g_1  = (const float*)d_in[9];
    const float* bt_1 = (const float*)d_in[10];
    const float* W2_1 = (const float*)d_in[11];
    const float* b2_1 = (const float*)d_in[12];
    const int* src = (const int*)d_in[13];
    const int* dst = (const int*)d_in[14];
    const int* gid = (const int*)d_in[15];
    float* out = (float*)d_out;

    const int copyBlocks    = (NND * DD / 4 + 255) / 256;
    const int scatterBlocks = (NE * 16 + 255) / 256;
    const int rowBlocks     = (NND + 127) / 128;
    const int statBlocks    = (NND + 1023) / 1024;

    k_zero_all<<<(NG * DD + 255) / 256, 256>>>();
    k_count<<<(NND + 255) / 256, 256>>>(gid);

    // ---- layer 0 ----
    k_copy<<<copyBlocks, 256>>>((const float4*)feats, -1, 0);
    k_scatter<<<scatterBlocks, 256>>>(feats, -1, 0, src, dst);
    k_lin1<<<rowBlocks, 128>>>(0, 1, W1_0, b1_0);
    k_bn_stats<<<statBlocks, 256>>>(1);
    k_bn_params<<<1, 64>>>(g_0, bt_0);
    k_mlp2<<<rowBlocks, 128>>>(1, 0, W2_0, b2_0, /*relu_out=*/1);

    // ---- layer 1 ----
    k_copy<<<copyBlocks, 256>>>(nullptr, 0, 1);
    k_scatter<<<scatterBlocks, 256>>>(nullptr, 0, 1, src, dst);
    k_zero_stats<<<1, 64>>>();
    k_lin1<<<rowBlocks, 128>>>(1, 0, W1_1, b1_1);
    k_bn_stats<<<statBlocks, 256>>>(0);
    k_bn_params<<<1, 64>>>(g_1, bt_1);
    k_mlp2<<<rowBlocks, 128>>>(0, 1, W2_1, b2_1, /*relu_out=*/0);

    // ---- readout ----
    k_pool<<<statBlocks, 256>>>(1, gid);
    k_finalize<<<(NG * DD + 255) / 256, 256>>>(out);
}

// round 2
// speedup vs baseline: 1.3625x; 1.3625x over previous
#include <cuda_runtime.h>

#define NND 100000
#define NE  1200000
#define DD  64
#define NG  100
#define BN_EPS 1e-5

// ---------------- scratch (device globals; no runtime allocation) ----------
__device__ float  g_bufA[NND * DD];
__device__ float  g_bufB[NND * DD];
__device__ double g_sum[DD];
__device__ double g_sumsq[DD];
__device__ float  g_scale[DD];
__device__ float  g_shift[DD];
__device__ float  g_pool[NG * DD];
__device__ int    g_cnt[NG];

__device__ __forceinline__ float* bufp(int b) { return b ? g_bufB : g_bufA; }

// ---------------- zeroing ---------------------------------------------------
__global__ void k_zero_all() {
    int t = blockIdx.x * blockDim.x + threadIdx.x;
    if (t < DD) { g_sum[t] = 0.0; g_sumsq[t] = 0.0; }
    if (t < NG * DD) g_pool[t] = 0.f;
    if (t < NG) g_cnt[t] = 0;
}

__global__ void k_zero_stats() {
    int t = threadIdx.x;
    if (t < DD) { g_sum[t] = 0.0; g_sumsq[t] = 0.0; }
}

// ---------------- copy (agg init: agg = h) ---------------------------------
__global__ void k_copy(const float4* __restrict__ ext, int srcsel, int dstb) {
    int t = blockIdx.x * blockDim.x + threadIdx.x;
    if (t >= NND * DD / 4) return;
    const float4* s = (srcsel < 0) ? ext : (const float4*)bufp(srcsel);
    ((float4*)bufp(dstb))[t] = s[t];
}

// ---------------- edge scatter: agg[dst] += h[src] --------------------------
// 16 threads per edge, each handles one float4 of the 64-wide row.
// Vector reduction: one red.global.add.v4.f32 instead of 4 scalar REDs.
__global__ void k_scatter(const float* ext, int srcsel, int dstb,
                          const int* __restrict__ src, const int* __restrict__ dst) {
    int t = blockIdx.x * blockDim.x + threadIdx.x;
    if (t >= NE * 16) return;
    int e = t >> 4;
    int c = t & 15;
    const float4* h = (const float4*)((srcsel < 0) ? ext : bufp(srcsel));
    int s = __ldg(src + e);
    int d = __ldg(dst + e);
    float4 v = __ldg(h + s * 16 + c);
    float4* p = (float4*)(bufp(dstb) + d * 64 + c * 4);
    asm volatile("red.global.add.v4.f32 [%0], {%1, %2, %3, %4};"
                 :: "l"(p), "f"(v.x), "f"(v.y), "f"(v.z), "f"(v.w)
                 : "memory");
}

// ---------------- Y = X @ W + b (thread per row, W in smem) -----------------
__global__ __launch_bounds__(128) void k_lin1(int inb, int outb,
        const float* __restrict__ W, const float* __restrict__ bias) {
    __shared__ float Ws[DD * DD];
    __shared__ float bs[DD];
    for (int i = threadIdx.x; i < DD * DD; i += 128) Ws[i] = W[i];
    if (threadIdx.x < DD) bs[threadIdx.x] = bias[threadIdx.x];
    __syncthreads();

    int row = blockIdx.x * 128 + threadIdx.x;
    if (row >= NND) return;
    const float* X = bufp(inb);
    float*       Y = bufp(outb);

    float x[DD];
    const float4* xp = (const float4*)(X + row * DD);
#pragma unroll
    for (int i = 0; i < 16; i++) {
        float4 v = xp[i];
        x[4 * i + 0] = v.x; x[4 * i + 1] = v.y; x[4 * i + 2] = v.z; x[4 * i + 3] = v.w;
    }

    float4* yp = (float4*)(Y + row * DD);
#pragma unroll 1
    for (int half = 0; half < 2; half++) {
        float acc[32];
#pragma unroll
        for (int j = 0; j < 32; j++) acc[j] = bs[half * 32 + j];
#pragma unroll
        for (int k = 0; k < DD; k++) {
            float xk = x[k];
            const float* wr = &Ws[k * DD + half * 32];
#pragma unroll
            for (int j = 0; j < 32; j++) acc[j] = fmaf(xk, wr[j], acc[j]);
        }
#pragma unroll
        for (int j = 0; j < 8; j++)
            yp[half * 8 + j] = make_float4(acc[4 * j], acc[4 * j + 1], acc[4 * j + 2], acc[4 * j + 3]);
    }
}

// ---------------- per-column sum / sumsq over rows (double accumulate) ------
__global__ void k_bn_stats(int inb) {
    const float* Y = bufp(inb);
    int col = threadIdx.x & 63;
    int rg  = threadIdx.x >> 6;          // 0..3
    int r0  = blockIdx.x * 1024 + rg * 256;
    float s = 0.f, sq = 0.f;
    for (int i = 0; i < 256; i++) {
        int r = r0 + i;
        if (r < NND) {
            float v = Y[r * 64 + col];
            s += v;
            sq += v * v;
        }
    }
    __shared__ float ss[256], ssq[256];
    ss[threadIdx.x] = s; ssq[threadIdx.x] = sq;
    __syncthreads();
    if (rg == 0) {
        float ts  = ss[col] + ss[64 + col] + ss[128 + col] + ss[192 + col];
        float tsq = ssq[col] + ssq[64 + col] + ssq[128 + col] + ssq[192 + col];
        atomicAdd(&g_sum[col], (double)ts);
        atomicAdd(&g_sumsq[col], (double)tsq);
    }
}

// ---------------- BN affine params ------------------------------------------
__global__ void k_bn_params(const float* __restrict__ gamma, const float* __restrict__ beta) {
    int j = threadIdx.x;
    if (j >= DD) return;
    double mu  = g_sum[j] / (double)NND;
    double var = g_sumsq[j] / (double)NND - mu * mu;
    double inv = rsqrt(var + (double)BN_EPS);
    g_scale[j] = (float)((double)gamma[j] * inv);
    g_shift[j] = (float)((double)beta[j] - mu * (double)gamma[j] * inv);
}

// ---------------- Out = [relu]( relu(BN(Ypre)) @ W2 + b2 ) ------------------
__global__ __launch_bounds__(128) void k_mlp2(int inb, int outb,
        const float* __restrict__ W, const float* __restrict__ bias, int relu_out) {
    __shared__ float Ws[DD * DD];
    __shared__ float bs[DD], sc[DD], sh[DD];
    for (int i = threadIdx.x; i < DD * DD; i += 128) Ws[i] = W[i];
    if (threadIdx.x < DD) {
        bs[threadIdx.x] = bias[threadIdx.x];
        sc[threadIdx.x] = g_scale[threadIdx.x];
        sh[threadIdx.x] = g_shift[threadIdx.x];
    }
    __syncthreads();

    int row = blockIdx.x * 128 + threadIdx.x;
    if (row >= NND) return;
    const float* X = bufp(inb);
    float*       Y = bufp(outb);

    float x[DD];
    const float4* xp = (const float4*)(X + row * DD);
#pragma unroll
    for (int i = 0; i < 16; i++) {
        float4 v = xp[i];
        x[4 * i + 0] = v.x; x[4 * i + 1] = v.y; x[4 * i + 2] = v.z; x[4 * i + 3] = v.w;
    }
#pragma unroll
    for (int k = 0; k < DD; k++)
        x[k] = fmaxf(fmaf(x[k], sc[k], sh[k]), 0.f);

    float4* yp = (float4*)(Y + row * DD);
#pragma unroll 1
    for (int half = 0; half < 2; half++) {
        float acc[32];
#pragma unroll
        for (int j = 0; j < 32; j++) acc[j] = bs[half * 32 + j];
#pragma unroll
        for (int k = 0; k < DD; k++) {
            float xk = x[k];
            const float* wr = &Ws[k * DD + half * 32];
#pragma unroll
            for (int j = 0; j < 32; j++) acc[j] = fmaf(xk, wr[j], acc[j]);
        }
        if (relu_out) {
#pragma unroll
            for (int j = 0; j < 32; j++) acc[j] = fmaxf(acc[j], 0.f);
        }
#pragma unroll
        for (int j = 0; j < 8; j++)
            yp[half * 8 + j] = make_float4(acc[4 * j], acc[4 * j + 1], acc[4 * j + 2], acc[4 * j + 3]);
    }
}

// ---------------- per-graph node counts -------------------------------------
__global__ void k_count(const int* __restrict__ gid) {
    int t = blockIdx.x * blockDim.x + threadIdx.x;
    if (t < NND) atomicAdd(&g_cnt[__ldg(gid + t)], 1);
}

// ---------------- mean-pool (graph_ids sorted: run-length accumulate) -------
__global__ void k_pool(int inb, const int* __restrict__ gid) {
    const float* H = bufp(inb);
    int col = threadIdx.x & 63;
    int rg  = threadIdx.x >> 6;
    int r0  = blockIdx.x * 1024 + rg * 256;
    int cur = -1;
    float acc = 0.f;
    for (int i = 0; i < 256; i++) {
        int r = r0 + i;
        if (r >= NND) break;
        int gi = __ldg(gid + r);
        if (gi != cur) {
            if (cur >= 0) atomicAdd(&g_pool[cur * DD + col], acc);
            cur = gi;
            acc = 0.f;
        }
        acc += H[r * 64 + col];
    }
    if (cur >= 0) atomicAdd(&g_pool[cur * DD + col], acc);
}

__global__ void k_finalize(float* __restrict__ out) {
    int t = blockIdx.x * blockDim.x + threadIdx.x;
    if (t < NG * DD) {
        int g = t / DD;
        int c = g_cnt[g];
        float cf = (float)(c > 0 ? c : 1);
        out[t] = g_pool[t] / cf;
    }
}

// ---------------- launch -----------------------------------------------------
extern "C" void kernel_launch(void* const* d_in, const int* in_sizes, int n_in,
                              void* d_out, int out_size) {
    const float* feats = (const float*)d_in[0];
    const float* W1_0 = (const float*)d_in[1];
    const float* b1_0 = (const float*)d_in[2];
    const float* g_0  = (const float*)d_in[3];
    const float* bt_0 = (const float*)d_in[4];
    const float* W2_0 = (const float*)d_in[5];
    const float* b2_0 = (const float*)d_in[6];
    const float* W1_1 = (const float*)d_in[7];
    const float* b1_1 = (const float*)d_in[8];
    const float* g_1  = (const float*)d_in[9];
    const float* bt_1 = (const float*)d_in[10];
    const float* W2_1 = (const float*)d_in[11];
    const float* b2_1 = (const float*)d_in[12];
    const int* src = (const int*)d_in[13];
    const int* dst = (const int*)d_in[14];
    const int* gid = (const int*)d_in[15];
    float* out = (float*)d_out;

    const int copyBlocks    = (NND * DD / 4 + 255) / 256;
    const int scatterBlocks = (NE * 16 + 255) / 256;
    const int rowBlocks     = (NND + 127) / 128;
    const int statBlocks    = (NND + 1023) / 1024;

    k_zero_all<<<(NG * DD + 255) / 256, 256>>>();
    k_count<<<(NND + 255) / 256, 256>>>(gid);

    // ---- layer 0 ----
    k_copy<<<copyBlocks, 256>>>((const float4*)feats, -1, 0);
    k_scatter<<<scatterBlocks, 256>>>(feats, -1, 0, src, dst);
    k_lin1<<<rowBlocks, 128>>>(0, 1, W1_0, b1_0);
    k_bn_stats<<<statBlocks, 256>>>(1);
    k_bn_params<<<1, 64>>>(g_0, bt_0);
    k_mlp2<<<rowBlocks, 128>>>(1, 0, W2_0, b2_0, /*relu_out=*/1);

    // ---- layer 1 ----
    k_copy<<<copyBlocks, 256>>>(nullptr, 0, 1);
    k_scatter<<<scatterBlocks, 256>>>(nullptr, 0, 1, src, dst);
    k_zero_stats<<<1, 64>>>();
    k_lin1<<<rowBlocks, 128>>>(1, 0, W1_1, b1_1);
    k_bn_stats<<<statBlocks, 256>>>(0);
    k_bn_params<<<1, 64>>>(g_1, bt_1);
    k_mlp2<<<rowBlocks, 128>>>(0, 1, W2_1, b2_1, /*relu_out=*/0);

    // ---- readout ----
    k_pool<<<statBlocks, 256>>>(1, gid);
    k_finalize<<<(NG * DD + 255) / 256, 256>>>(out);
}

// round 3
// speedup vs baseline: 1.3667x; 1.0031x over previous
#include <cuda_runtime.h>

#define NND 100000
#define NE  1200000
#define DD  64
#define NG  100
#define BN_EPS 1e-5

// ---------------- scratch (device globals; no runtime allocation) ----------
__device__ float  g_bufA[NND * DD];
__device__ float  g_bufB[NND * DD];
__device__ double g_sum[DD];
__device__ double g_sumsq[DD];
__device__ float  g_scale[DD];
__device__ float  g_shift[DD];
__device__ float  g_pool[NG * DD];
__device__ int    g_cnt[NG];

__device__ __forceinline__ float* bufp(int b) { return b ? g_bufB : g_bufA; }

// ---------------- zeroing ---------------------------------------------------
__global__ void k_zero_all() {
    int t = blockIdx.x * blockDim.x + threadIdx.x;
    if (t < DD) { g_sum[t] = 0.0; g_sumsq[t] = 0.0; }
    if (t < NG * DD) g_pool[t] = 0.f;
    if (t < NG) g_cnt[t] = 0;
}

__global__ void k_zero_stats() {
    int t = threadIdx.x;
    if (t < DD) { g_sum[t] = 0.0; g_sumsq[t] = 0.0; }
}

// ---------------- copy (agg init: agg = h) ---------------------------------
__global__ void k_copy(const float4* __restrict__ ext, int srcsel, int dstb) {
    int t = blockIdx.x * blockDim.x + threadIdx.x;
    if (t >= NND * DD / 4) return;
    const float4* s = (srcsel < 0) ? ext : (const float4*)bufp(srcsel);
    ((float4*)bufp(dstb))[t] = s[t];
}

// ---------------- edge scatter: agg[dst] += h[src] --------------------------
// 16 threads per edge, each handles one float4 of the 64-wide row.
// Vector reduction: one red.global.add.v4.f32 instead of 4 scalar REDs.
__global__ void k_scatter(const float* ext, int srcsel, int dstb,
                          const int* __restrict__ src, const int* __restrict__ dst) {
    int t = blockIdx.x * blockDim.x + threadIdx.x;
    if (t >= NE * 16) return;
    int e = t >> 4;
    int c = t & 15;
    const float4* h = (const float4*)((srcsel < 0) ? ext : bufp(srcsel));
    int s = __ldg(src + e);
    int d = __ldg(dst + e);
    float4 v = __ldg(h + s * 16 + c);
    float4* p = (float4*)(bufp(dstb) + d * 64 + c * 4);
    asm volatile("red.global.add.v4.f32 [%0], {%1, %2, %3, %4};"
                 :: "l"(p), "f"(v.x), "f"(v.y), "f"(v.z), "f"(v.w)
                 : "memory");
}

// ---------------- Y = X @ W + b (thread per row, W in smem) -----------------
__global__ __launch_bounds__(128) void k_lin1(int inb, int outb,
        const float* __restrict__ W, const float* __restrict__ bias) {
    __shared__ float Ws[DD * DD];
    __shared__ float bs[DD];
    for (int i = threadIdx.x; i < DD * DD; i += 128) Ws[i] = W[i];
    if (threadIdx.x < DD) bs[threadIdx.x] = bias[threadIdx.x];
    __syncthreads();

    int row = blockIdx.x * 128 + threadIdx.x;
    if (row >= NND) return;
    const float* X = bufp(inb);
    float*       Y = bufp(outb);

    float x[DD];
    const float4* xp = (const float4*)(X + row * DD);
#pragma unroll
    for (int i = 0; i < 16; i++) {
        float4 v = xp[i];
        x[4 * i + 0] = v.x; x[4 * i + 1] = v.y; x[4 * i + 2] = v.z; x[4 * i + 3] = v.w;
    }

    float4* yp = (float4*)(Y + row * DD);
#pragma unroll 1
    for (int half = 0; half < 2; half++) {
        float acc[32];
#pragma unroll
        for (int j = 0; j < 32; j++) acc[j] = bs[half * 32 + j];
#pragma unroll
        for (int k = 0; k < DD; k++) {
            float xk = x[k];
            const float* wr = &Ws[k * DD + half * 32];
#pragma unroll
            for (int j = 0; j < 32; j++) acc[j] = fmaf(xk, wr[j], acc[j]);
        }
#pragma unroll
        for (int j = 0; j < 8; j++)
            yp[half * 8 + j] = make_float4(acc[4 * j], acc[4 * j + 1], acc[4 * j + 2], acc[4 * j + 3]);
    }
}

// ---------------- per-column sum / sumsq over rows (double accumulate) ------
__global__ void k_bn_stats(int inb) {
    const float* Y = bufp(inb);
    int col = threadIdx.x & 63;
    int rg  = threadIdx.x >> 6;          // 0..3
    int r0  = blockIdx.x * 1024 + rg * 256;
    float s = 0.f, sq = 0.f;
    for (int i = 0; i < 256; i++) {
        int r = r0 + i;
        if (r < NND) {
            float v = Y[r * 64 + col];
            s += v;
            sq += v * v;
        }
    }
    __shared__ float ss[256], ssq[256];
    ss[threadIdx.x] = s; ssq[threadIdx.x] = sq;
    __syncthreads();
    if (rg == 0) {
        float ts  = ss[col] + ss[64 + col] + ss[128 + col] + ss[192 + col];
        float tsq = ssq[col] + ssq[64 + col] + ssq[128 + col] + ssq[192 + col];
        atomicAdd(&g_sum[col], (double)ts);
        atomicAdd(&g_sumsq[col], (double)tsq);
    }
}

// ---------------- BN affine params ------------------------------------------
__global__ void k_bn_params(const float* __restrict__ gamma, const float* __restrict__ beta) {
    int j = threadIdx.x;
    if (j >= DD) return;
    double mu  = g_sum[j] / (double)NND;
    double var = g_sumsq[j] / (double)NND - mu * mu;
    double inv = rsqrt(var + (double)BN_EPS);
    g_scale[j] = (float)((double)gamma[j] * inv);
    g_shift[j] = (float)((double)beta[j] - mu * (double)gamma[j] * inv);
}

// ---------------- Out = [relu]( relu(BN(Ypre)) @ W2 + b2 ) ------------------
__global__ __launch_bounds__(128) void k_mlp2(int inb, int outb,
        const float* __restrict__ W, const float* __restrict__ bias, int relu_out) {
    __shared__ float Ws[DD * DD];
    __shared__ float bs[DD], sc[DD], sh[DD];
    for (int i = threadIdx.x; i < DD * DD; i += 128) Ws[i] = W[i];
    if (threadIdx.x < DD) {
        bs[threadIdx.x] = bias[threadIdx.x];
        sc[threadIdx.x] = g_scale[threadIdx.x];
        sh[threadIdx.x] = g_shift[threadIdx.x];
    }
    __syncthreads();

    int row = blockIdx.x * 128 + threadIdx.x;
    if (row >= NND) return;
    const float* X = bufp(inb);
    float*       Y = bufp(outb);

    float x[DD];
    const float4* xp = (const float4*)(X + row * DD);
#pragma unroll
    for (int i = 0; i < 16; i++) {
        float4 v = xp[i];
        x[4 * i + 0] = v.x; x[4 * i + 1] = v.y; x[4 * i + 2] = v.z; x[4 * i + 3] = v.w;
    }
#pragma unroll
    for (int k = 0; k < DD; k++)
        x[k] = fmaxf(fmaf(x[k], sc[k], sh[k]), 0.f);

    float4* yp = (float4*)(Y + row * DD);
#pragma unroll 1
    for (int half = 0; half < 2; half++) {
        float acc[32];
#pragma unroll
        for (int j = 0; j < 32; j++) acc[j] = bs[half * 32 + j];
#pragma unroll
        for (int k = 0; k < DD; k++) {
            float xk = x[k];
            const float* wr = &Ws[k * DD + half * 32];
#pragma unroll
            for (int j = 0; j < 32; j++) acc[j] = fmaf(xk, wr[j], acc[j]);
        }
        if (relu_out) {
#pragma unroll
            for (int j = 0; j < 32; j++) acc[j] = fmaxf(acc[j], 0.f);
        }
#pragma unroll
        for (int j = 0; j < 8; j++)
            yp[half * 8 + j] = make_float4(acc[4 * j], acc[4 * j + 1], acc[4 * j + 2], acc[4 * j + 3]);
    }
}

// ---------------- per-graph node counts -------------------------------------
__global__ void k_count(const int* __restrict__ gid) {
    int t = blockIdx.x * blockDim.x + threadIdx.x;
    if (t < NND) atomicAdd(&g_cnt[__ldg(gid + t)], 1);
}

// ---------------- mean-pool (graph_ids sorted: run-length accumulate) -------
__global__ void k_pool(int inb, const int* __restrict__ gid) {
    const float* H = bufp(inb);
    int col = threadIdx.x & 63;
    int rg  = threadIdx.x >> 6;
    int r0  = blockIdx.x * 1024 + rg * 256;
    int cur = -1;
    float acc = 0.f;
    for (int i = 0; i < 256; i++) {
        int r = r0 + i;
        if (r >= NND) break;
        int gi = __ldg(gid + r);
        if (gi != cur) {
            if (cur >= 0) atomicAdd(&g_pool[cur * DD + col], acc);
            cur = gi;
            acc = 0.f;
        }
        acc += H[r * 64 + col];
    }
    if (cur >= 0) atomicAdd(&g_pool[cur * DD + col], acc);
}

__global__ void k_finalize(float* __restrict__ out) {
    int t = blockIdx.x * blockDim.x + threadIdx.x;
    if (t < NG * DD) {
        int g = t / DD;
        int c = g_cnt[g];
        float cf = (float)(c > 0 ? c : 1);
        out[t] = g_pool[t] / cf;
    }
}

// ---------------- launch -----------------------------------------------------
extern "C" void kernel_launch(void* const* d_in, const int* in_sizes, int n_in,
                              void* d_out, int out_size) {
    const float* feats = (const float*)d_in[0];
    const float* W1_0 = (const float*)d_in[1];
    const float* b1_0 = (const float*)d_in[2];
    const float* g_0  = (const float*)d_in[3];
    const float* bt_0 = (const float*)d_in[4];
    const float* W2_0 = (const float*)d_in[5];
    const float* b2_0 = (const float*)d_in[6];
    const float* W1_1 = (const float*)d_in[7];
    const float* b1_1 = (const float*)d_in[8];
    const float* g_1  = (const float*)d_in[9];
    const float* bt_1 = (const float*)d_in[10];
    const float* W2_1 = (const float*)d_in[11];
    const float* b2_1 = (const float*)d_in[12];
    const int* src = (const int*)d_in[13];
    const int* dst = (const int*)d_in[14];
    const int* gid = (const int*)d_in[15];
    float* out = (float*)d_out;

    const int copyBlocks    = (NND * DD / 4 + 255) / 256;
    const int scatterBlocks = (NE * 16 + 255) / 256;
    const int rowBlocks     = (NND + 127) / 128;
    const int statBlocks    = (NND + 1023) / 1024;

    k_zero_all<<<(NG * DD + 255) / 256, 256>>>();
    k_count<<<(NND + 255) / 256, 256>>>(gid);

    // ---- layer 0 ----
    k_copy<<<copyBlocks, 256>>>((const float4*)feats, -1, 0);
    k_scatter<<<scatterBlocks, 256>>>(feats, -1, 0, src, dst);
    k_lin1<<<rowBlocks, 128>>>(0, 1, W1_0, b1_0);
    k_bn_stats<<<statBlocks, 256>>>(1);
    k_bn_params<<<1, 64>>>(g_0, bt_0);
    k_mlp2<<<rowBlocks, 128>>>(1, 0, W2_0, b2_0, /*relu_out=*/1);

    // ---- layer 1 ----
    k_copy<<<copyBlocks, 256>>>(nullptr, 0, 1);
    k_scatter<<<scatterBlocks, 256>>>(nullptr, 0, 1, src, dst);
    k_zero_stats<<<1, 64>>>();
    k_lin1<<<rowBlocks, 128>>>(1, 0, W1_1, b1_1);
    k_bn_stats<<<statBlocks, 256>>>(0);
    k_bn_params<<<1, 64>>>(g_1, bt_1);
    k_mlp2<<<rowBlocks, 128>>>(0, 1, W2_1, b2_1, /*relu_out=*/0);

    // ---- readout ----
    k_pool<<<statBlocks, 256>>>(1, gid);
    k_finalize<<<(NG * DD + 255) / 256, 256>>>(out);
}